// round 9
// baseline (speedup 1.0000x reference)
#include <cuda_runtime.h>

#define T_LEN   1024
#define PHASE_L 16
#define NPH     (T_LEN / PHASE_L)   // 64 phases
#define NGRP    (T_LEN / 4)         // 256 x-groups
#define QPB     8                   // batch elements per block
#define LPB     (QPB * 4)           // 32 lanes per role
#define BLOCKT  96                  // warp0=L0 cell, warp1=L1 cell, warp2=helper

typedef unsigned long long u64;

__device__ __forceinline__ float tanhaf(float x){ float r; asm("tanh.approx.f32 %0, %1;" : "=f"(r) : "f"(x)); return r; }
__device__ __forceinline__ u64 pk2(float a, float b){ u64 r; asm("mov.b64 %0, {%1, %2};" : "=l"(r) : "f"(a), "f"(b)); return r; }
__device__ __forceinline__ void upk2(u64 v, float &a, float &b){ asm("mov.b64 {%0, %1}, %2;" : "=f"(a), "=f"(b) : "l"(v)); }
__device__ __forceinline__ u64 ffma2(u64 a, u64 b, u64 c){ u64 d; asm("fma.rn.f32x2 %0, %1, %2, %3;" : "=l"(d) : "l"(a), "l"(b), "l"(c)); return d; }

__global__ void __launch_bounds__(BLOCKT, 1)
lstm_pipe3_kernel(const float* __restrict__ x,
                  const float* __restrict__ Wih0, const float* __restrict__ Whh0,
                  const float* __restrict__ bih0, const float* __restrict__ bhh0,
                  const float* __restrict__ Wih1, const float* __restrict__ Whh1,
                  const float* __restrict__ bih1, const float* __restrict__ bhh1,
                  const float* __restrict__ W1,   const float* __restrict__ b1,
                  const float* __restrict__ W2,   const float* __restrict__ b2,
                  float* __restrict__ yout, int B)
{
    // Pipeline buffers (double-buffered by phase parity).
    // pq*: per-step, per-lane precomputed gate inputs {P=(i,f), Q=(g,o)} incl. bias.
    // STS/LDS pattern: 32 lanes x 16B contiguous per step -> conflict-free .128 ops.
    __shared__ ulonglong2 pq0[2][PHASE_L][LPB];
    __shared__ ulonglong2 pq1[2][PHASE_L][LPB];
    __shared__ float4     hb0[2][PHASE_L][QPB];
    __shared__ float4     hb1[2][PHASE_L][QPB];

    const int tid  = threadIdx.x;
    const int wid  = tid >> 5;       // 0 = L0 cell, 1 = L1 cell, 2 = helper
    const int l    = tid & 31;
    const int quad = l >> 2;         // batch element within block
    const int j    = l & 3;          // hidden unit owned by this lane
    const int b    = blockIdx.x * QPB + quad;
    const bool alive = (b < B);
    const unsigned FULL = 0xffffffffu;
    const int ri = j, rf = 4 + j, rg = 8 + j, ro = 12 + j;

    // ---- cell recurrence weights (xor-permuted: column = j ^ m, so term 0 is own-lane)
    // sigmoid(v) = 0.5 + 0.5*tanh(v/2): 1/2 pre-scale folded into i,f,o rows.
    u64 ph[4], qh[4];
    if (wid == 0) {
#pragma unroll
        for (int m = 0; m < 4; ++m) {
            int cm = j ^ m;
            ph[m] = pk2(0.5f * Whh0[ri*4+cm], 0.5f * Whh0[rf*4+cm]);
            qh[m] = pk2(       Whh0[rg*4+cm], 0.5f * Whh0[ro*4+cm]);
        }
    } else if (wid == 1) {
#pragma unroll
        for (int m = 0; m < 4; ++m) {
            int cm = j ^ m;
            ph[m] = pk2(0.5f * Whh1[ri*4+cm], 0.5f * Whh1[rf*4+cm]);
            qh[m] = pk2(       Whh1[rg*4+cm], 0.5f * Whh1[ro*4+cm]);
        }
    }

    // ---- helper weights: input GEMMs (biases folded) + MLP head
    u64 px0[3], qx0[3], pb0, qb0, px1[4], qx1[4], pb1, qb1;
    float4 w1r0, w1r1, w1r2, w1r3, b1v, w2v;
    float b2c = 0.f;
    if (wid == 2) {
#pragma unroll
        for (int k = 0; k < 3; ++k) {
            px0[k] = pk2(0.5f * Wih0[ri*3+k], 0.5f * Wih0[rf*3+k]);
            qx0[k] = pk2(       Wih0[rg*3+k], 0.5f * Wih0[ro*3+k]);
        }
        pb0 = pk2(0.5f*(bih0[ri]+bhh0[ri]), 0.5f*(bih0[rf]+bhh0[rf]));
        qb0 = pk2(     (bih0[rg]+bhh0[rg]), 0.5f*(bih0[ro]+bhh0[ro]));
#pragma unroll
        for (int m = 0; m < 4; ++m) {
            px1[m] = pk2(0.5f * Wih1[ri*4+m], 0.5f * Wih1[rf*4+m]);
            qx1[m] = pk2(       Wih1[rg*4+m], 0.5f * Wih1[ro*4+m]);
        }
        pb1 = pk2(0.5f*(bih1[ri]+bhh1[ri]), 0.5f*(bih1[rf]+bhh1[rf]));
        qb1 = pk2(     (bih1[rg]+bhh1[rg]), 0.5f*(bih1[ro]+bhh1[ro]));
        // head: each lane handles timesteps t%4 == j of its quad -> needs full W1
        const float4* W1v = reinterpret_cast<const float4*>(W1);
        w1r0 = __ldg(W1v + 0); w1r1 = __ldg(W1v + 1);
        w1r2 = __ldg(W1v + 2); w1r3 = __ldg(W1v + 3);
        b1v  = *reinterpret_cast<const float4*>(b1);
        w2v  = *reinterpret_cast<const float4*>(W2);
        b2c  = b2[0];
    }

    // ---- recurrent state (cell warps)
    float cst = 0.f, hst = 0.f;

    const float4* __restrict__ xr = reinterpret_cast<const float4*>(x + (size_t)b * (3*T_LEN));
    float* __restrict__ yr = yout + (size_t)b * T_LEN;

    // helper x prefetch (current 4-step group)
    float4 curA, curB, curC;
    if (wid == 2) {
        if (alive) {
            curA = __ldg(xr + 0); curB = __ldg(xr + 1); curC = __ldg(xr + 2);
        } else {
            curA = curB = curC = make_float4(0.f,0.f,0.f,0.f);
        }
    }

    // Pipeline (iteration k):  helper-x0 -> phase k | L0 -> k-1 | helper-x1 -> k-2
    //                          | L1 -> k-3 | helper-head -> k-4
#pragma unroll 1
    for (int k = 0; k <= NPH + 3; ++k) {
        if (wid <= 1) {
            const int p = k - 1 - 2*wid;              // L0: k-1, L1: k-3
            if (p >= 0 && p < NPH) {
                ulonglong2 (*pqb)[LPB] = (wid == 0) ? pq0[p & 1] : pq1[p & 1];
                float4     (*hbb)[QPB] = (wid == 0) ? hb0[p & 1] : hb1[p & 1];
                ulonglong2 cur[4], nxt[4];
#pragma unroll
                for (int s = 0; s < 4; ++s) cur[s] = pqb[s][l];
#pragma unroll
                for (int g = 0; g < 4; ++g) {
                    if (g < 3) {
#pragma unroll
                        for (int s = 0; s < 4; ++s) nxt[s] = pqb[(g+1)*4 + s][l];
                    }
#pragma unroll
                    for (int s = 0; s < 4; ++s) {
                        // ---- LSTM cell: only the recurrence lives here
                        u64 hbc = pk2(hst, hst);
                        float s1 = __shfl_xor_sync(FULL, hst, 1, 4);
                        float s2 = __shfl_xor_sync(FULL, hst, 2, 4);
                        float s3 = __shfl_xor_sync(FULL, hst, 3, 4);
                        u64 P = ffma2(ph[0], hbc, cur[s].x);
                        u64 Q = ffma2(qh[0], hbc, cur[s].y);
                        u64 v1 = pk2(s1, s1), v2 = pk2(s2, s2), v3 = pk2(s3, s3);
                        P = ffma2(ph[1], v1, P);  Q = ffma2(qh[1], v1, Q);
                        P = ffma2(ph[2], v2, P);  Q = ffma2(qh[2], v2, Q);
                        P = ffma2(ph[3], v3, P);  Q = ffma2(qh[3], v3, Q);
                        float pi, pf, pg, po;
                        upk2(P, pi, pf); upk2(Q, pg, po);
                        float ti = tanhaf(pi), tf = tanhaf(pf), tg = tanhaf(pg), to = tanhaf(po);
                        float iv = fmaf(0.5f, ti, 0.5f);
                        float fv = fmaf(0.5f, tf, 0.5f);
                        float ov = fmaf(0.5f, to, 0.5f);
                        cst = fmaf(fv, cst, iv * tg);
                        hst = ov * tanhaf(cst);
                        ((float*)&hbb[g*4 + s][quad])[j] = hst;
                    }
#pragma unroll
                    for (int s = 0; s < 4; ++s) cur[s] = nxt[s];
                }
            }
        } else {
            // ================= helper =================
            // -- x0-part: gate inputs for phase k from gmem x
            if (k < NPH) {
#pragma unroll
                for (int g = 0; g < 4; ++g) {
                    const int G = k*4 + g;
                    const int Gn = (G + 1 < NGRP) ? (G + 1) : G;
                    float4 nA, nB, nC;
                    if (alive) {
                        nA = __ldg(xr + 3*Gn + 0);
                        nB = __ldg(xr + 3*Gn + 1);
                        nC = __ldg(xr + 3*Gn + 2);
                    } else {
                        nA = nB = nC = make_float4(0.f,0.f,0.f,0.f);
                    }
                    float xs[4][3] = {
                        {curA.x, curA.y, curA.z},
                        {curA.w, curB.x, curB.y},
                        {curB.z, curB.w, curC.x},
                        {curC.y, curC.z, curC.w},
                    };
#pragma unroll
                    for (int s = 0; s < 4; ++s) {
                        u64 x0 = pk2(xs[s][0], xs[s][0]);
                        u64 x1 = pk2(xs[s][1], xs[s][1]);
                        u64 x2 = pk2(xs[s][2], xs[s][2]);
                        u64 Px = ffma2(px0[0], x0, pb0);
                        u64 Qx = ffma2(qx0[0], x0, qb0);
                        Px = ffma2(px0[1], x1, Px);  Qx = ffma2(qx0[1], x1, Qx);
                        Px = ffma2(px0[2], x2, Px);  Qx = ffma2(qx0[2], x2, Qx);
                        pq0[k & 1][g*4 + s][l] = make_ulonglong2(Px, Qx);
                    }
                    curA = nA; curB = nB; curC = nC;
                }
            }
            // -- x1-part: gate inputs for L1 from h0 of phase k-2
            if (k >= 2 && k <= NPH + 1) {
                const int p = k - 2;
#pragma unroll
                for (int t = 0; t < PHASE_L; ++t) {
                    float4 hv = hb0[p & 1][t][quad];
                    u64 x0 = pk2(hv.x, hv.x), x1 = pk2(hv.y, hv.y);
                    u64 x2 = pk2(hv.z, hv.z), x3 = pk2(hv.w, hv.w);
                    u64 Px = ffma2(px1[0], x0, pb1);
                    u64 Qx = ffma2(qx1[0], x0, qb1);
                    Px = ffma2(px1[1], x1, Px);  Qx = ffma2(qx1[1], x1, Qx);
                    Px = ffma2(px1[2], x2, Px);  Qx = ffma2(qx1[2], x2, Qx);
                    Px = ffma2(px1[3], x3, Px);  Qx = ffma2(qx1[3], x3, Qx);
                    pq1[p & 1][t][l] = make_ulonglong2(Px, Qx);
                }
            }
            // -- head: y for phase k-4 from h1 (lane j handles steps t%4==j)
            if (k >= 4) {
                const int p = k - 4;
#pragma unroll
                for (int g = 0; g < 4; ++g) {
                    const int tl = g*4 + j;
                    float4 hv = hb1[p & 1][tl][quad];
                    float z0 = fmaf(w1r0.x, hv.x, fmaf(w1r0.y, hv.y, fmaf(w1r0.z, hv.z, fmaf(w1r0.w, hv.w, b1v.x))));
                    float z1 = fmaf(w1r1.x, hv.x, fmaf(w1r1.y, hv.y, fmaf(w1r1.z, hv.z, fmaf(w1r1.w, hv.w, b1v.y))));
                    float z2 = fmaf(w1r2.x, hv.x, fmaf(w1r2.y, hv.y, fmaf(w1r2.z, hv.z, fmaf(w1r2.w, hv.w, b1v.z))));
                    float z3 = fmaf(w1r3.x, hv.x, fmaf(w1r3.y, hv.y, fmaf(w1r3.z, hv.z, fmaf(w1r3.w, hv.w, b1v.w))));
                    float t0 = tanhaf(z0), t1 = tanhaf(z1), t2 = tanhaf(z2), t3 = tanhaf(z3);
                    float yv = fmaf(w2v.x, t0, fmaf(w2v.y, t1, fmaf(w2v.z, t2, fmaf(w2v.w, t3, b2c))));
                    if (alive) yr[p*PHASE_L + tl] = yv;
                }
            }
        }
        __syncthreads();
    }
}

extern "C" void kernel_launch(void* const* d_in, const int* in_sizes, int n_in,
                              void* d_out, int out_size)
{
    const float* x    = (const float*)d_in[0];
    const float* Wih0 = (const float*)d_in[1];
    const float* Whh0 = (const float*)d_in[2];
    const float* bih0 = (const float*)d_in[3];
    const float* bhh0 = (const float*)d_in[4];
    const float* Wih1 = (const float*)d_in[5];
    const float* Whh1 = (const float*)d_in[6];
    const float* bih1 = (const float*)d_in[7];
    const float* bhh1 = (const float*)d_in[8];
    const float* W1   = (const float*)d_in[9];
    const float* b1   = (const float*)d_in[10];
    const float* W2   = (const float*)d_in[11];
    const float* b2   = (const float*)d_in[12];

    int B = out_size / T_LEN;                 // output is [B, T, 1]
    int grid = (B + QPB - 1) / QPB;           // 512 blocks for B=4096
    lstm_pipe3_kernel<<<grid, BLOCKT>>>(x, Wih0, Whh0, bih0, bhh0,
                                        Wih1, Whh1, bih1, bhh1,
                                        W1, b1, W2, b2,
                                        (float*)d_out, B);
}